// round 13
// baseline (speedup 1.0000x reference)
#include <cuda_runtime.h>
#include <math.h>

#define BATCH 2048
#define TT 512
#define PP 8
#define LL 64
#define HH 180
#define ROWS 16
#define NTHREADS 512

typedef unsigned long long u64;

// ---- packed f32x2 helpers (Blackwell FFMA2 path) ----
__device__ __forceinline__ u64 pack2(float w) {
    u64 r; asm("mov.b64 %0, {%1, %1};" : "=l"(r) : "f"(w)); return r;
}
__device__ __forceinline__ void fma2(u64 &acc, u64 x, u64 w) {
    asm("fma.rn.f32x2 %0, %1, %2, %3;" : "=l"(acc) : "l"(x), "l"(w), "l"(acc));
}
__device__ __forceinline__ void unpack2(u64 v, float &lo, float &hi) {
    asm("mov.b64 {%0, %1}, %2;" : "=f"(lo), "=f"(hi) : "l"(v));
}

__device__ __forceinline__ float gelu_f(float x) {
    return 0.5f * x * (1.0f + erff(x * 0.70710678118654752440f));
}
__device__ __forceinline__ float sigm_f(float x) {
    return 1.0f / (1.0f + expf(-x));
}

// Warp-tile worker: thread computes NP row-pairs x 3 consecutive output cols.
// srcT: [K][16] transposed activations in SMEM. w*p: rows of W ([col][K], k-contig).
template<int NP, int ACT, int K>
__device__ __forceinline__ void mma3(
    const float* __restrict__ srcT,
    const float* __restrict__ w0p, const float* __restrict__ w1p, const float* __restrict__ w2p,
    int pr, float b0, float b1, float b2,
    float* __restrict__ d0, float* __restrict__ d1, float* __restrict__ d2)
{
    u64 acc[3][NP];
#pragma unroll
    for (int c = 0; c < 3; ++c)
#pragma unroll
        for (int p = 0; p < NP; ++p) acc[c][p] = 0ull;

    const float4* W0 = (const float4*)w0p;
    const float4* W1 = (const float4*)w1p;
    const float4* W2 = (const float4*)w2p;
    const int K4 = K >> 2;
#pragma unroll 3
    for (int kk = 0; kk < K4; ++kk) {
        float4 f0 = W0[kk];
        float4 f1 = W1[kk];
        float4 f2 = W2[kk];
        const float* a0 = (const float*)&f0;
        const float* a1 = (const float*)&f1;
        const float* a2 = (const float*)&f2;
#pragma unroll
        for (int u = 0; u < 4; ++u) {
            const int k = (kk << 2) + u;
            u64 xv[NP];
#pragma unroll
            for (int p = 0; p < NP; ++p)
                xv[p] = *(const u64*)(srcT + k * 16 + (pr + p) * 2);
            u64 wv0 = pack2(a0[u]);
            u64 wv1 = pack2(a1[u]);
            u64 wv2 = pack2(a2[u]);
#pragma unroll
            for (int p = 0; p < NP; ++p) {
                fma2(acc[0][p], xv[p], wv0);
                fma2(acc[1][p], xv[p], wv1);
                fma2(acc[2][p], xv[p], wv2);
            }
        }
    }
    float bb[3] = {b0, b1, b2};
    float* dd[3] = {d0, d1, d2};
#pragma unroll
    for (int c = 0; c < 3; ++c) {
#pragma unroll
        for (int p = 0; p < NP; ++p) {
            float lo, hi;
            unpack2(acc[c][p], lo, hi);
            lo += bb[c]; hi += bb[c];
            if (ACT == 1) { lo = gelu_f(lo); hi = gelu_f(hi); }
            *(float2*)(dd[c] + (pr + p) * 2) = make_float2(lo, hi);
        }
    }
}

// SMEM float offsets
#define OFF_CAT1 0        // [72][16]   = 1152  (also delta staging: 1024)
#define OFF_XT   1152     // [180][16]  = 2880
#define OFF_HC   4032     // [244][16]  = 3904  (h rows 0..179, cur rows 180..243)
#define OFF_G    7936     // [1080][16] = 17280
#define OFF_O1   25216    // [180][16]  = 2880
#define OFF_BIAS 28096    // 1684
#define SMEM_FLOATS 29780

__global__ void __launch_bounds__(NTHREADS, 1)
latent_rnn_kernel(const float* __restrict__ phys,
                  const float* __restrict__ latents,
                  const float* __restrict__ W_in,  const float* __restrict__ b_in,
                  const float* __restrict__ W_hp,  const float* __restrict__ b_hp,
                  const float* __restrict__ W_ih,  const float* __restrict__ b_ih,
                  const float* __restrict__ W_hh,  const float* __restrict__ b_hh,
                  const float* __restrict__ W_o1,  const float* __restrict__ b_o1,
                  const float* __restrict__ W_o2,  const float* __restrict__ b_o2,
                  float* __restrict__ out)
{
    extern __shared__ float sm[];
    float* s_cat1 = sm + OFF_CAT1;
    float* s_xT   = sm + OFF_XT;
    float* s_hc   = sm + OFF_HC;
    float* s_g    = sm + OFF_G;
    float* s_o1T  = sm + OFF_O1;
    float* s_bias = sm + OFF_BIAS;

    const int tid  = threadIdx.x;
    const int w    = tid >> 5;
    const int lane = tid & 31;
    const int r0   = blockIdx.x * ROWS;

    // ---- preload all biases into SMEM ----
    for (int i = tid; i < 1684; i += NTHREADS) {
        float v;
        if (i < 180)       v = b_in[i];
        else if (i < 720)  v = b_ih[i - 180];
        else if (i < 1260) v = b_hh[i - 720];
        else if (i < 1440) v = b_o1[i - 1260];
        else if (i < 1504) v = b_o2[i - 1440];
        else               v = b_hp[i - 1504];
        s_bias[i] = v;
    }
    // ---- latents -> cur state rows + h0-GEMM source (transposed) ----
    for (int e = tid; e < LL * ROWS; e += NTHREADS) {
        int c = e >> 4, r = e & 15;
        float v = latents[(size_t)(r0 + r) * LL + c];
        s_cat1[c * 16 + r]      = v;
        s_hc[(HH + c) * 16 + r] = v;
    }
    __syncthreads();

    // ---- h0 = latents @ W_hp^T + b_hp  (K=64, N=180 -> 15 warp tiles of 12 cols) ----
    if (w < 15) {
        int rb = lane & 7, cb = lane >> 3;
        int col = w * 12 + cb * 3;
        mma3<1, 0, 64>(s_cat1,
                       W_hp + col * 64, W_hp + (col + 1) * 64, W_hp + (col + 2) * 64,
                       rb, s_bias[1504 + col], s_bias[1505 + col], s_bias[1506 + col],
                       s_hc + col * 16, s_hc + (col + 1) * 16, s_hc + (col + 2) * 16);
    }
    __syncthreads();

    // ==================== time loop ====================
    for (int t = 0; t < TT; ++t) {
        // build phase-1 input [phys_t(8) ; cur(64)] transposed
        if (tid < 128) {
            int r = tid >> 3, p = tid & 7;
            s_cat1[p * 16 + r] = phys[((size_t)(r0 + r) * TT + t) * PP + p];
        }
        for (int e = tid; e < LL * ROWS; e += NTHREADS) {
            int c = e >> 4, r = e & 15;
            s_cat1[(PP + c) * 16 + r] = s_hc[(HH + c) * 16 + r];
        }
        __syncthreads();

        // phase 1: x = gelu(cat1 @ W_in^T + b_in)   (K=72, N=180)
        if (w < 15) {
            int rb = lane & 7, cb = lane >> 3;
            int col = w * 12 + cb * 3;
            mma3<1, 1, 72>(s_cat1,
                           W_in + col * 72, W_in + (col + 1) * 72, W_in + (col + 2) * 72,
                           rb, s_bias[col], s_bias[col + 1], s_bias[col + 2],
                           s_xT + col * 16, s_xT + (col + 1) * 16, s_xT + (col + 2) * 16);
        }
        __syncthreads();

        // phase 2: gi (cols 0..539, src x) | gh (cols 540..1079, src h), K=180
        {
            int rb = lane & 3, cb = lane >> 2;
#pragma unroll
            for (int it = 0; it < 3; ++it) {
                int tl = w + (it << 4);
                if (tl < 45) {
                    int col = tl * 24 + cb * 3;
                    const float* src; const float* wp; const float* bp;
                    if (col < 540) { src = s_xT; wp = W_ih + col * 180;         bp = s_bias + 180 + col; }
                    else           { src = s_hc; wp = W_hh + (col - 540) * 180; bp = s_bias + 720 + (col - 540); }
                    mma3<2, 0, 180>(src, wp, wp + 180, wp + 360,
                                    rb * 2, bp[0], bp[1], bp[2],
                                    s_g + col * 16, s_g + (col + 1) * 16, s_g + (col + 2) * 16);
                }
            }
        }
        __syncthreads();

        // gates: GRU update, h_new written in place
        for (int e = tid; e < HH * ROWS; e += NTHREADS) {
            int j = e >> 4, r = e & 15;
            float rr = sigm_f(s_g[j * 16 + r]         + s_g[(540 + j) * 16 + r]);
            float zz = sigm_f(s_g[(180 + j) * 16 + r] + s_g[(720 + j) * 16 + r]);
            float nn = tanhf (s_g[(360 + j) * 16 + r] + rr * s_g[(900 + j) * 16 + r]);
            float h  = s_hc[j * 16 + r];
            s_hc[j * 16 + r] = (1.0f - zz) * nn + zz * h;
        }
        __syncthreads();

        // phase 3: o1 = gelu([h_new ; cur] @ W_o1^T + b_o1)   (K=244, N=180)
        if (w < 15) {
            int rb = lane & 7, cb = lane >> 3;
            int col = w * 12 + cb * 3;
            mma3<1, 1, 244>(s_hc,
                            W_o1 + col * 244, W_o1 + (col + 1) * 244, W_o1 + (col + 2) * 244,
                            rb, s_bias[1260 + col], s_bias[1261 + col], s_bias[1262 + col],
                            s_o1T + col * 16, s_o1T + (col + 1) * 16, s_o1T + (col + 2) * 16);
        }
        __syncthreads();

        // phase 4: delta = o1 @ W_o2^T + b_o2; cur = clip(cur+delta, 0, 1)
        for (int e = tid; e < LL * ROWS; e += NTHREADS) {
            int l = e >> 4, r = e & 15;
            float acc = s_bias[1440 + l];
            const float4* wp = (const float4*)(W_o2 + l * 180);
#pragma unroll 9
            for (int kk = 0; kk < 45; ++kk) {
                float4 wv = wp[kk];
                int kb = kk << 2;
                acc = fmaf(wv.x, s_o1T[kb * 16 + r], acc);
                acc = fmaf(wv.y, s_o1T[(kb + 1) * 16 + r], acc);
                acc = fmaf(wv.z, s_o1T[(kb + 2) * 16 + r], acc);
                acc = fmaf(wv.w, s_o1T[(kb + 3) * 16 + r], acc);
            }
            float cur = s_hc[(HH + l) * 16 + r];
            float cn = fminf(fmaxf(cur + acc, 0.0f), 1.0f);
            s_hc[(HH + l) * 16 + r] = cn;
            s_cat1[r * 64 + l] = cn;   // stage for coalesced store
        }
        __syncthreads();

        // coalesced output store  out[b, t, l]
        for (int e = tid; e < LL * ROWS; e += NTHREADS) {
            int l = e & 63, r = e >> 6;
            out[((size_t)(r0 + r) * TT + t) * LL + l] = s_cat1[r * 64 + l];
        }
        __syncthreads();
    }
}

extern "C" void kernel_launch(void* const* d_in, const int* in_sizes, int n_in,
                              void* d_out, int out_size)
{
    const float* phys    = (const float*)d_in[0];
    const float* latents = (const float*)d_in[1];
    const float* W_in    = (const float*)d_in[2];
    const float* b_in    = (const float*)d_in[3];
    const float* W_hp    = (const float*)d_in[4];
    const float* b_hp    = (const float*)d_in[5];
    const float* W_ih    = (const float*)d_in[6];
    const float* b_ih    = (const float*)d_in[7];
    const float* W_hh    = (const float*)d_in[8];
    const float* b_hh    = (const float*)d_in[9];
    const float* W_o1    = (const float*)d_in[10];
    const float* b_o1    = (const float*)d_in[11];
    const float* W_o2    = (const float*)d_in[12];
    const float* b_o2    = (const float*)d_in[13];
    float* out = (float*)d_out;

    size_t smem = (size_t)SMEM_FLOATS * sizeof(float);
    cudaFuncSetAttribute(latent_rnn_kernel,
                         cudaFuncAttributeMaxDynamicSharedMemorySize, (int)smem);
    latent_rnn_kernel<<<BATCH / ROWS, NTHREADS, smem>>>(
        phys, latents, W_in, b_in, W_hp, b_hp, W_ih, b_ih, W_hh, b_hh,
        W_o1, b_o1, W_o2, b_o2, out);
}